// round 2
// baseline (speedup 1.0000x reference)
#include <cuda_runtime.h>
#include <cuda_bf16.h>
#include <math.h>

// Problem constants (fixed by the reference):
//   Q, K, V: (16, 2048, 256) fp32 ; padding_mask: (16, 2048) int32 ; out: (16, 2048, 256) fp32
#define BATCH    16
#define SEQ      2048
#define DIM      256
#define BR       64     // q rows per CTA
#define BC       64     // k cols per tile
#define QSTR     260    // padded smem row stride (floats) for Q
#define KSTR     260    // padded smem row stride (floats) for K
#define VSTR     256
#define PSTR     64
#define NTHREADS 256

// dynamic smem layout (floats):
//   Qs[BR*QSTR] | Ks[BC*KSTR] | Vs[BC*VSTR] | Ps[BR*PSTR] | pads[BC] (as ints)
#define SMEM_FLOATS (BR*QSTR + BC*KSTR + BC*VSTR + BR*PSTR)
#define SMEM_BYTES  (SMEM_FLOATS * 4 + BC * 4)

__device__ __forceinline__ float redmax16(float v) {
#pragma unroll
    for (int m = 8; m >= 1; m >>= 1)
        v = fmaxf(v, __shfl_xor_sync(0xffffffffu, v, m));
    return v;
}

__device__ __forceinline__ float redsum16(float v) {
#pragma unroll
    for (int m = 8; m >= 1; m >>= 1)
        v += __shfl_xor_sync(0xffffffffu, v, m);
    return v;
}

__global__ __launch_bounds__(NTHREADS, 1)
void attn_fwd_fp32(const float* __restrict__ Qg, const float* __restrict__ Kg,
                   const float* __restrict__ Vg, const int* __restrict__ pad,
                   float* __restrict__ Og) {
    extern __shared__ float sm[];
    float* Qs = sm;                         // BR x QSTR
    float* Ks = Qs + BR * QSTR;             // BC x KSTR
    float* Vs = Ks + BC * KSTR;             // BC x VSTR
    float* Ps = Vs + BC * VSTR;             // BR x PSTR
    int*   pads = (int*)(Ps + BR * PSTR);   // BC

    const int qt  = blockIdx.x;             // q-tile index (0..31)
    const int b   = blockIdx.y;             // batch
    const int tid = threadIdx.x;
    const int tx  = tid & 15;               // 0..15: score-col group / out-col group
    const int ty  = tid >> 4;               // 0..15: q-row group

    // ---- load Q tile (64 x 256) into padded smem ----
    {
        const float4* Q4 = (const float4*)(Qg + ((size_t)b * SEQ + (size_t)qt * BR) * DIM);
#pragma unroll
        for (int t = tid; t < BR * (DIM / 4); t += NTHREADS) {
            int row = t >> 6, c4 = t & 63;
            float4 v = Q4[row * (DIM / 4) + c4];
            *(float4*)&Qs[row * QSTR + c4 * 4] = v;
        }
    }

    // per-thread state: 4 q-rows (ty*4+i), 16 out cols (tx*16 + c)
    float o[4][16];
#pragma unroll
    for (int i = 0; i < 4; i++)
#pragma unroll
        for (int c = 0; c < 16; c++) o[i][c] = 0.f;
    float mrow[4], lrow[4];
#pragma unroll
    for (int i = 0; i < 4; i++) { mrow[i] = -INFINITY; lrow[i] = 0.f; }

    const float scale = 0.0625f;  // 1/sqrt(256)

    for (int j0 = 0; j0 <= qt; ++j0) {
        __syncthreads();  // previous iter's smem reads (K/V/P) done, Q load done (iter 0)

        // ---- load K/V tile (64 x 256 each) + pad slice ----
        {
            const size_t baseK = ((size_t)b * SEQ + (size_t)j0 * BC) * DIM;
            const float4* K4 = (const float4*)(Kg + baseK);
            const float4* V4 = (const float4*)(Vg + baseK);
#pragma unroll
            for (int t = tid; t < BC * (DIM / 4); t += NTHREADS) {
                int row = t >> 6, c4 = t & 63;
                *(float4*)&Ks[row * KSTR + c4 * 4] = K4[row * (DIM / 4) + c4];
                *(float4*)&Vs[row * VSTR + c4 * 4] = V4[row * (DIM / 4) + c4];
            }
            if (tid < BC) pads[tid] = pad[(size_t)b * SEQ + (size_t)j0 * BC + tid];
        }
        __syncthreads();

        // ---- S = Q K^T  (4 rows x 4 strided cols per thread) ----
        float s[4][4];
#pragma unroll
        for (int i = 0; i < 4; i++)
#pragma unroll
            for (int j = 0; j < 4; j++) s[i][j] = 0.f;

#pragma unroll 2
        for (int d = 0; d < DIM; d += 4) {
            float qv[4][4], kv[4][4];
#pragma unroll
            for (int i = 0; i < 4; i++)
                *(float4*)qv[i] = *(const float4*)&Qs[(ty * 4 + i) * QSTR + d];
#pragma unroll
            for (int j = 0; j < 4; j++)
                *(float4*)kv[j] = *(const float4*)&Ks[(tx + 16 * j) * KSTR + d];
#pragma unroll
            for (int i = 0; i < 4; i++)
#pragma unroll
                for (int j = 0; j < 4; j++) {
                    s[i][j] += qv[i][0] * kv[j][0];
                    s[i][j] += qv[i][1] * kv[j][1];
                    s[i][j] += qv[i][2] * kv[j][2];
                    s[i][j] += qv[i][3] * kv[j][3];
                }
        }

        // ---- mask + scale ----
#pragma unroll
        for (int i = 0; i < 4; i++) {
            const int qg = qt * BR + ty * 4 + i;
#pragma unroll
            for (int j = 0; j < 4; j++) {
                const int kcol = tx + 16 * j;
                const int kg = j0 * BC + kcol;
                float sv = s[i][j] * scale;
                if (kg > qg || pads[kcol] == 0) sv = -INFINITY;
                s[i][j] = sv;
            }
        }

        // ---- online softmax update + write P ----
#pragma unroll
        for (int i = 0; i < 4; i++) {
            float rm = fmaxf(fmaxf(s[i][0], s[i][1]), fmaxf(s[i][2], s[i][3]));
            rm = redmax16(rm);
            const float nm = fmaxf(mrow[i], rm);
            const float corr = __expf(mrow[i] - nm);
            float rs = 0.f;
#pragma unroll
            for (int j = 0; j < 4; j++) {
                float p = __expf(s[i][j] - nm);
                s[i][j] = p;
                rs += p;
            }
            rs = redsum16(rs);
            lrow[i] = lrow[i] * corr + rs;
            mrow[i] = nm;
#pragma unroll
            for (int c = 0; c < 16; c++) o[i][c] *= corr;
#pragma unroll
            for (int j = 0; j < 4; j++)
                Ps[(ty * 4 + i) * PSTR + tx + 16 * j] = s[i][j];
        }
        __syncthreads();

        // ---- O += P V  (4 rows x 16 cols per thread, k = 0..63) ----
#pragma unroll 1
        for (int kk = 0; kk < BC; kk += 4) {
            float pr[4][4];
#pragma unroll
            for (int i = 0; i < 4; i++)
                *(float4*)pr[i] = *(const float4*)&Ps[(ty * 4 + i) * PSTR + kk];
#pragma unroll
            for (int s4 = 0; s4 < 4; s4++) {
                float vv[16];
#pragma unroll
                for (int c4 = 0; c4 < 4; c4++)
                    *(float4*)&vv[c4 * 4] =
                        *(const float4*)&Vs[(kk + s4) * VSTR + tx * 16 + c4 * 4];
#pragma unroll
                for (int i = 0; i < 4; i++) {
                    const float p = pr[i][s4];
#pragma unroll
                    for (int c = 0; c < 16; c++) o[i][c] += p * vv[c];
                }
            }
        }
    }

    // ---- epilogue: normalize and store ----
#pragma unroll
    for (int i = 0; i < 4; i++) {
        const float inv = 1.0f / lrow[i];
        float* orow = Og + ((size_t)b * SEQ + (size_t)(qt * BR + ty * 4 + i)) * DIM + tx * 16;
#pragma unroll
        for (int c4 = 0; c4 < 4; c4++) {
            float4 v;
            v.x = o[i][c4 * 4 + 0] * inv;
            v.y = o[i][c4 * 4 + 1] * inv;
            v.z = o[i][c4 * 4 + 2] * inv;
            v.w = o[i][c4 * 4 + 3] * inv;
            *(float4*)&orow[c4 * 4] = v;
        }
    }
}

extern "C" void kernel_launch(void* const* d_in, const int* in_sizes, int n_in,
                              void* d_out, int out_size) {
    const float* Q   = (const float*)d_in[0];
    const float* K   = (const float*)d_in[1];
    const float* V   = (const float*)d_in[2];
    const int*   pad = (const int*)d_in[3];
    float*       O   = (float*)d_out;

    cudaFuncSetAttribute(attn_fwd_fp32,
                         cudaFuncAttributeMaxDynamicSharedMemorySize, SMEM_BYTES);

    dim3 grid(SEQ / BR, BATCH);
    attn_fwd_fp32<<<grid, NTHREADS, SMEM_BYTES>>>(Q, K, V, pad, O);
}

// round 6
// speedup vs baseline: 6.2257x; 6.2257x over previous
#include <cuda_runtime.h>
#include <cuda_bf16.h>
#include <stdint.h>
#include <math.h>

#define SEQ 2048
#define DIM 256
#define NTH 256

// ---- smem byte offsets (no overlaps: PADS 0-256, PMAX 256-768, PSUM 768-1280) ----
#define SM_PADS 0
#define SM_PMAX 256
#define SM_PSUM 768
#define SM_QH   1536
#define SM_QL   34304
#define SM_KH   67072
#define SM_KL   99840
#define SM_VH   132608
#define SM_VL   165376
#define SM_PH   198144
#define SM_PL   206336
#define SMEM_TOTAL 214528

// pre-converted bf16 hi/lo tensors, pre-swizzled: row r, 16B chunk c stored at c ^ (r&7)
#define ROWS_T (16 * 2048)
__device__ uint4 gQH[ROWS_T * 32];
__device__ uint4 gQL[ROWS_T * 32];
__device__ uint4 gKH[ROWS_T * 32];
__device__ uint4 gKL[ROWS_T * 32];
__device__ uint4 gVH[ROWS_T * 32];
__device__ uint4 gVL[ROWS_T * 32];

__device__ __forceinline__ uint32_t smem_u32(const void* p) {
    uint32_t a;
    asm("{ .reg .u64 t; cvta.to.shared.u64 t, %1; cvt.u32.u64 %0, t; }" : "=r"(a) : "l"(p));
    return a;
}
__device__ __forceinline__ void cpa16(uint32_t dst, const void* src) {
    asm volatile("cp.async.cg.shared.global [%0], [%1], 16;" :: "r"(dst), "l"(src) : "memory");
}
#define CP_COMMIT() asm volatile("cp.async.commit_group;" ::: "memory")
#define CP_WAIT(n)  asm volatile("cp.async.wait_group %0;" :: "n"(n) : "memory")

__device__ __forceinline__ void ldsm4(uint32_t r[4], uint32_t a) {
    asm volatile("ldmatrix.sync.aligned.m8n8.x4.shared.b16 {%0,%1,%2,%3}, [%4];"
                 : "=r"(r[0]), "=r"(r[1]), "=r"(r[2]), "=r"(r[3]) : "r"(a));
}
__device__ __forceinline__ void ldsm4t(uint32_t r[4], uint32_t a) {
    asm volatile("ldmatrix.sync.aligned.m8n8.x4.trans.shared.b16 {%0,%1,%2,%3}, [%4];"
                 : "=r"(r[0]), "=r"(r[1]), "=r"(r[2]), "=r"(r[3]) : "r"(a));
}
__device__ __forceinline__ void mma16816(float c[4], const uint32_t a[4], uint32_t b0, uint32_t b1) {
    asm volatile("mma.sync.aligned.m16n8k16.row.col.f32.bf16.bf16.f32 "
                 "{%0,%1,%2,%3}, {%4,%5,%6,%7}, {%8,%9}, {%0,%1,%2,%3};"
                 : "+f"(c[0]), "+f"(c[1]), "+f"(c[2]), "+f"(c[3])
                 : "r"(a[0]), "r"(a[1]), "r"(a[2]), "r"(a[3]), "r"(b0), "r"(b1));
}
__device__ __forceinline__ float ex2(float x) {
    float y; asm("ex2.approx.f32 %0, %1;" : "=f"(y) : "f"(x)); return y;
}
__device__ __forceinline__ uint32_t pack2(__nv_bfloat16 a, __nv_bfloat16 b) {
    return ((uint32_t)__bfloat16_as_ushort(b) << 16) | (uint32_t)__bfloat16_as_ushort(a);
}
__device__ __forceinline__ uint32_t packlo(float a, float b) {  // low<-a, high<-b
    uint32_t r; asm("cvt.rn.bf16x2.f32 %0, %1, %2;" : "=r"(r) : "f"(b), "f"(a)); return r;
}
__device__ __forceinline__ void split_pair(float x, float y, uint32_t& hi, uint32_t& lo) {
    __nv_bfloat16 hx = __float2bfloat16_rn(x);
    __nv_bfloat16 hy = __float2bfloat16_rn(y);
    hi = pack2(hx, hy);
    lo = packlo(x - __bfloat162float(hx), y - __bfloat162float(hy));
}

// ---------------- pre-pass: fp32 -> swizzled bf16 hi/lo ----------------
__global__ __launch_bounds__(256)
void prepass(const float* __restrict__ Q, const float* __restrict__ K,
             const float* __restrict__ V) {
    const float QSC = 0.0901684400555602f;  // log2(e)/16
    int g = blockIdx.x * 256 + threadIdx.x; // 3 * 2^20 threads
    int t = g >> 20;
    int r = (g >> 5) & 32767;
    int c = g & 31;
    const float* src = (t == 0) ? Q : ((t == 1) ? K : V);
    float sc = (t == 0) ? QSC : 1.0f;
    const float4* s4 = (const float4*)src + (size_t)r * 64 + c * 2;
    float4 a = s4[0], b = s4[1];
    a.x *= sc; a.y *= sc; a.z *= sc; a.w *= sc;
    b.x *= sc; b.y *= sc; b.z *= sc; b.w *= sc;
    uint32_t h0, l0, h1, l1, h2, l2, h3, l3;
    split_pair(a.x, a.y, h0, l0); split_pair(a.z, a.w, h1, l1);
    split_pair(b.x, b.y, h2, l2); split_pair(b.z, b.w, h3, l3);
    uint4* dh = (t == 0) ? gQH : ((t == 1) ? gKH : gVH);
    uint4* dl = (t == 0) ? gQL : ((t == 1) ? gKL : gVL);
    int off = r * 32 + (c ^ (r & 7));
    dh[off] = make_uint4(h0, h1, h2, h3);
    dl[off] = make_uint4(l0, l1, l2, l3);
}

// ---------------- main attention kernel ----------------
__global__ __launch_bounds__(NTH, 1)
void attn_mma(const int* __restrict__ pad, float* __restrict__ Og) {
    extern __shared__ char smem[];
    const uint32_t smb = smem_u32(smem);
    const int tid = threadIdx.x, lane = tid & 31, wid = tid >> 5;
    const int wr = wid & 3;         // row-group: rows 16*wr .. 16*wr+15
    const int h  = wid >> 2;        // column half
    const int bx = blockIdx.x;
    const int qt = 31 - (bx >> 4);  // big q-tiles first (LPT)
    const int b  = bx & 15;

    float* pmax = (float*)(smem + SM_PMAX);
    float* psum = (float*)(smem + SM_PSUM);
    int*  padsm = (int*)(smem + SM_PADS);

    // prologue: Q hi/lo -> persistent smem; then K(0)
    {
        const uint4* qh = gQH + (size_t)(b * SEQ + qt * 64) * 32;
        const uint4* ql = gQL + (size_t)(b * SEQ + qt * 64) * 32;
        for (int g = tid; g < 2048; g += NTH) {
            cpa16(smb + SM_QH + g * 16, qh + g);
            cpa16(smb + SM_QL + g * 16, ql + g);
        }
        CP_COMMIT();
        const uint4* kh = gKH + (size_t)(b * SEQ) * 32;
        const uint4* kl = gKL + (size_t)(b * SEQ) * 32;
        for (int g = tid; g < 2048; g += NTH) {
            cpa16(smb + SM_KH + g * 16, kh + g);
            cpa16(smb + SM_KL + g * 16, kl + g);
        }
        CP_COMMIT();
    }

    float o[16][4];
#pragma unroll
    for (int i = 0; i < 16; i++) { o[i][0] = 0.f; o[i][1] = 0.f; o[i][2] = 0.f; o[i][3] = 0.f; }
    float mA = -INFINITY, mB = -INFINITY, lA = 0.f, lB = 0.f;
    const int rloc = 16 * wr + (lane >> 2);   // local q-row A; row B = +8
    const int grA  = qt * 64 + rloc;

    const int ntiles = qt + 1;
    for (int j0 = 0; j0 < ntiles; ++j0) {
        __syncthreads();  // prior PV done reading V
        {   // issue V(j0)
            const uint4* vh = gVH + (size_t)(b * SEQ + j0 * 64) * 32;
            const uint4* vl = gVL + (size_t)(b * SEQ + j0 * 64) * 32;
            for (int g = tid; g < 2048; g += NTH) {
                cpa16(smb + SM_VH + g * 16, vh + g);
                cpa16(smb + SM_VL + g * 16, vl + g);
            }
            CP_COMMIT();
        }
        if (tid < 64) padsm[tid] = pad[(size_t)b * SEQ + (size_t)j0 * 64 + tid];
        CP_WAIT(1);       // K(j0) (and Q on iter 0) complete
        __syncthreads();

        // ---- S = Qh*Kh + Qh*Kl + Ql*Kh  (16 rows x 32 cols per warp) ----
        float s[4][4];
#pragma unroll
        for (int j = 0; j < 4; j++) { s[j][0] = 0.f; s[j][1] = 0.f; s[j][2] = 0.f; s[j][3] = 0.f; }
        {
            const int qr = 16 * wr + (lane & 15);
            const int qc = (lane >> 4) & 1;
            const int krow = 32 * h + (lane & 7) + (((lane >> 4) & 1) << 3);
            const int kc = (lane >> 3) & 1;
#pragma unroll
            for (int ks = 0; ks < 16; ks++) {
                uint32_t qh[4], ql[4];
                uint32_t qsw = (uint32_t)(((2 * ks + qc) ^ (qr & 7)) << 4);
                ldsm4(qh, smb + SM_QH + qr * 512 + qsw);
                ldsm4(ql, smb + SM_QL + qr * 512 + qsw);
                uint32_t csw = (uint32_t)(((2 * ks + kc) ^ (lane & 7)) << 4);
                uint32_t kh0[4], kh1[4], kl0[4], kl1[4];
                ldsm4(kh0, smb + SM_KH + krow * 512 + csw);
                ldsm4(kh1, smb + SM_KH + (krow + 16) * 512 + csw);
                ldsm4(kl0, smb + SM_KL + krow * 512 + csw);
                ldsm4(kl1, smb + SM_KL + (krow + 16) * 512 + csw);
                mma16816(s[0], qh, kh0[0], kh0[1]);
                mma16816(s[0], qh, kl0[0], kl0[1]);
                mma16816(s[0], ql, kh0[0], kh0[1]);
                mma16816(s[1], qh, kh0[2], kh0[3]);
                mma16816(s[1], qh, kl0[2], kl0[3]);
                mma16816(s[1], ql, kh0[2], kh0[3]);
                mma16816(s[2], qh, kh1[0], kh1[1]);
                mma16816(s[2], qh, kl1[0], kl1[1]);
                mma16816(s[2], ql, kh1[0], kh1[1]);
                mma16816(s[3], qh, kh1[2], kh1[3]);
                mma16816(s[3], qh, kl1[2], kl1[3]);
                mma16816(s[3], ql, kh1[2], kh1[3]);
            }
        }

        // ---- mask + rowmax ----
        uint32_t pm0 = __ballot_sync(0xffffffffu, padsm[lane] != 0);
        uint32_t pm1 = __ballot_sync(0xffffffffu, padsm[lane + 32] != 0);
        const uint32_t pmsel = h ? pm1 : pm0;
        const int limA = grA - j0 * 64 - 32 * h;
        const int limB = limA + 8;
        const int cb = (lane & 3) * 2;
        float rmA = -INFINITY, rmB = -INFINITY;
#pragma unroll
        for (int j = 0; j < 4; j++) {
#pragma unroll
            for (int e = 0; e < 2; e++) {
                const int cl = 8 * j + cb + e;
                const bool okp = (pmsel >> cl) & 1u;
                float v = s[j][e];
                if (cl > limA || !okp) v = -INFINITY;
                s[j][e] = v; rmA = fmaxf(rmA, v);
                float w = s[j][2 + e];
                if (cl > limB || !okp) w = -INFINITY;
                s[j][2 + e] = w; rmB = fmaxf(rmB, w);
            }
        }
        rmA = fmaxf(rmA, __shfl_xor_sync(0xffffffffu, rmA, 1));
        rmA = fmaxf(rmA, __shfl_xor_sync(0xffffffffu, rmA, 2));
        rmB = fmaxf(rmB, __shfl_xor_sync(0xffffffffu, rmB, 1));
        rmB = fmaxf(rmB, __shfl_xor_sync(0xffffffffu, rmB, 2));
        if ((lane & 3) == 0) {
            pmax[h * 64 + rloc] = rmA;
            pmax[h * 64 + rloc + 8] = rmB;
        }
        __syncthreads();  // pmax visible; all warps done reading K

        if (j0 + 1 < ntiles) {  // issue K(j0+1)
            const uint4* kh = gKH + (size_t)(b * SEQ + (j0 + 1) * 64) * 32;
            const uint4* kl = gKL + (size_t)(b * SEQ + (j0 + 1) * 64) * 32;
            for (int g = tid; g < 2048; g += NTH) {
                cpa16(smb + SM_KH + g * 16, kh + g);
                cpa16(smb + SM_KL + g * 16, kl + g);
            }
        }
        CP_COMMIT();

        // ---- softmax + P hi/lo -> smem + O rescale ----
        const float nmA = fmaxf(mA, fmaxf(pmax[rloc], pmax[64 + rloc]));
        const float nmB = fmaxf(mB, fmaxf(pmax[rloc + 8], pmax[64 + rloc + 8]));
        const float corrA = (nmA == -INFINITY) ? 1.f : ex2(mA - nmA);
        const float corrB = (nmB == -INFINITY) ? 1.f : ex2(mB - nmB);
        const float nmsA = (nmA == -INFINITY) ? 0.f : nmA;
        const float nmsB = (nmB == -INFINITY) ? 0.f : nmB;
        float sumA = 0.f, sumB = 0.f;
#pragma unroll
        for (int j = 0; j < 4; j++) {
            float p0 = ex2(s[j][0] - nmsA);
            float p1 = ex2(s[j][1] - nmsA);
            float p2 = ex2(s[j][2] - nmsB);
            float p3 = ex2(s[j][3] - nmsB);
            sumA += p0 + p1; sumB += p2 + p3;
            uint32_t phA, plA, phB, plB;
            split_pair(p0, p1, phA, plA);
            split_pair(p2, p3, phB, plB);
            const int ch = 4 * h + j;
            const uint32_t offA = rloc * 128 + ((ch ^ (rloc & 7)) << 4) + (lane & 3) * 4;
            const uint32_t offB = offA + 8 * 128;
            *(uint32_t*)(smem + SM_PH + offA) = phA;
            *(uint32_t*)(smem + SM_PL + offA) = plA;
            *(uint32_t*)(smem + SM_PH + offB) = phB;
            *(uint32_t*)(smem + SM_PL + offB) = plB;
        }
        sumA += __shfl_xor_sync(0xffffffffu, sumA, 1);
        sumA += __shfl_xor_sync(0xffffffffu, sumA, 2);
        sumB += __shfl_xor_sync(0xffffffffu, sumB, 1);
        sumB += __shfl_xor_sync(0xffffffffu, sumB, 2);
        if ((lane & 3) == 0) {
            psum[h * 64 + rloc] = sumA;
            psum[h * 64 + rloc + 8] = sumB;
        }
#pragma unroll
        for (int nt = 0; nt < 16; nt++) {
            o[nt][0] *= corrA; o[nt][1] *= corrA;
            o[nt][2] *= corrB; o[nt][3] *= corrB;
        }
        CP_WAIT(1);   // V(j0) complete (K(j0+1) in flight)
        __syncthreads();
        lA = lA * corrA + psum[rloc] + psum[64 + rloc];
        lB = lB * corrB + psum[rloc + 8] + psum[64 + rloc + 8];
        mA = nmA; mB = nmB;

        // ---- O += Ph*Vh + Ph*Vl + Pl*Vh  (16 rows x 128 cols per warp) ----
        {
            const int pr = 16 * wr + (lane & 15);
            const int pc = (lane >> 4) & 1;
            const int vrow = (lane & 7) + (((lane >> 3) & 1) << 3);
            const int vca = (lane >> 4) & 1;
#pragma unroll
            for (int ks = 0; ks < 4; ks++) {
                uint32_t ph[4], pl[4];
                const uint32_t poff = (uint32_t)(pr * 128 + (((2 * ks + pc) ^ (pr & 7)) << 4));
                ldsm4(ph, smb + SM_PH + poff);
                ldsm4(pl, smb + SM_PL + poff);
                const uint32_t vbase = (uint32_t)((16 * ks + vrow) * 512);
#pragma unroll
                for (int np = 0; np < 8; np++) {
                    const int c0 = 16 * h + 2 * np + vca;
                    const uint32_t voff = vbase + (uint32_t)(((c0 ^ (lane & 7)) << 4));
                    uint32_t vh[4], vl[4];
                    ldsm4t(vh, smb + SM_VH + voff);
                    ldsm4t(vl, smb + SM_VL + voff);
                    mma16816(o[2 * np], ph, vh[0], vh[1]);
                    mma16816(o[2 * np], ph, vl[0], vl[1]);
                    mma16816(o[2 * np], pl, vh[0], vh[1]);
                    mma16816(o[2 * np + 1], ph, vh[2], vh[3]);
                    mma16816(o[2 * np + 1], ph, vl[2], vl[3]);
                    mma16816(o[2 * np + 1], pl, vh[2], vh[3]);
                }
            }
        }
    }

    // ---- epilogue ----
    const float invA = 1.0f / lA;
    const float invB = 1.0f / lB;
    const size_t rowA = (size_t)b * SEQ + (size_t)(qt * 64 + rloc);
    float* oa = Og + rowA * DIM + 128 * h + (lane & 3) * 2;
    float* ob = oa + 8 * DIM;
#pragma unroll
    for (int nt = 0; nt < 16; nt++) {
        float2 va = make_float2(o[nt][0] * invA, o[nt][1] * invA);
        float2 vb = make_float2(o[nt][2] * invB, o[nt][3] * invB);
        *(float2*)(oa + 8 * nt) = va;
        *(float2*)(ob + 8 * nt) = vb;
    }
}

extern "C" void kernel_launch(void* const* d_in, const int* in_sizes, int n_in,
                              void* d_out, int out_size) {
    const float* Q   = (const float*)d_in[0];
    const float* K   = (const float*)d_in[1];
    const float* V   = (const float*)d_in[2];
    const int*   pad = (const int*)d_in[3];
    float*       O   = (float*)d_out;

    prepass<<<12288, 256>>>(Q, K, V);
    cudaFuncSetAttribute(attn_mma, cudaFuncAttributeMaxDynamicSharedMemorySize, SMEM_TOTAL);
    attn_mma<<<512, NTH, SMEM_TOTAL>>>(pad, O);
}

// round 7
// speedup vs baseline: 7.2206x; 1.1598x over previous
#include <cuda_runtime.h>
#include <cuda_fp16.h>
#include <stdint.h>
#include <math.h>

#define SEQ 2048
#define DIM 256
#define NTH 256

// ---- smem byte offsets ----
#define SM_PADS 0
#define SM_PMAX 256
#define SM_PSUM 768
#define SM_Q16  1536
#define SM_KH   34304
#define SM_KL   67072
#define SM_VH   99840
#define SM_VL   132608
#define SM_PH   165376
#define SMEM_TOTAL 173568

// pre-converted fp16 tensors, pre-swizzled: row r, 16B chunk c stored at c ^ (r&7)
#define ROWS_T (16 * 2048)
__device__ uint4 gQ16[ROWS_T * 32];
__device__ uint4 gKH[ROWS_T * 32];
__device__ uint4 gKL[ROWS_T * 32];
__device__ uint4 gVH[ROWS_T * 32];
__device__ uint4 gVL[ROWS_T * 32];

__device__ __forceinline__ uint32_t smem_u32(const void* p) {
    uint32_t a;
    asm("{ .reg .u64 t; cvta.to.shared.u64 t, %1; cvt.u32.u64 %0, t; }" : "=r"(a) : "l"(p));
    return a;
}
__device__ __forceinline__ void cpa16(uint32_t dst, const void* src) {
    asm volatile("cp.async.cg.shared.global [%0], [%1], 16;" :: "r"(dst), "l"(src) : "memory");
}
#define CP_COMMIT() asm volatile("cp.async.commit_group;" ::: "memory")
#define CP_WAIT(n)  asm volatile("cp.async.wait_group %0;" :: "n"(n) : "memory")
#define PAIR_BAR(id) asm volatile("bar.sync %0, 64;" :: "r"((id) + 1) : "memory")

__device__ __forceinline__ void ldsm4(uint32_t r[4], uint32_t a) {
    asm volatile("ldmatrix.sync.aligned.m8n8.x4.shared.b16 {%0,%1,%2,%3}, [%4];"
                 : "=r"(r[0]), "=r"(r[1]), "=r"(r[2]), "=r"(r[3]) : "r"(a));
}
__device__ __forceinline__ void ldsm4t(uint32_t r[4], uint32_t a) {
    asm volatile("ldmatrix.sync.aligned.m8n8.x4.trans.shared.b16 {%0,%1,%2,%3}, [%4];"
                 : "=r"(r[0]), "=r"(r[1]), "=r"(r[2]), "=r"(r[3]) : "r"(a));
}
__device__ __forceinline__ void mmah(float c[4], const uint32_t a[4], uint32_t b0, uint32_t b1) {
    asm volatile("mma.sync.aligned.m16n8k16.row.col.f32.f16.f16.f32 "
                 "{%0,%1,%2,%3}, {%4,%5,%6,%7}, {%8,%9}, {%0,%1,%2,%3};"
                 : "+f"(c[0]), "+f"(c[1]), "+f"(c[2]), "+f"(c[3])
                 : "r"(a[0]), "r"(a[1]), "r"(a[2]), "r"(a[3]), "r"(b0), "r"(b1));
}
__device__ __forceinline__ float ex2(float x) {
    float y; asm("ex2.approx.f32 %0, %1;" : "=f"(y) : "f"(x)); return y;
}
__device__ __forceinline__ uint32_t packh(float a, float b) {  // low<-a, high<-b
    uint32_t r; asm("cvt.rn.f16x2.f32 %0, %1, %2;" : "=r"(r) : "f"(b), "f"(a)); return r;
}
__device__ __forceinline__ void split_pair(float x, float y, uint32_t& hi, uint32_t& lo) {
    __half hx = __float2half_rn(x);
    __half hy = __float2half_rn(y);
    hi = ((uint32_t)__half_as_ushort(hy) << 16) | (uint32_t)__half_as_ushort(hx);
    lo = packh(x - __half2float(hx), y - __half2float(hy));
}

// ---------------- pre-pass: fp32 -> swizzled fp16 (Q single; K,V hi/lo) ----------------
__global__ __launch_bounds__(256)
void prepass(const float* __restrict__ Q, const float* __restrict__ K,
             const float* __restrict__ V) {
    const float QSC = 0.0901684400555602f;  // log2(e)/16
    int g = blockIdx.x * 256 + threadIdx.x; // 3 * 2^20 threads
    int t = g >> 20;
    int r = (g >> 5) & 32767;
    int c = g & 31;
    const float* src = (t == 0) ? Q : ((t == 1) ? K : V);
    float sc = (t == 0) ? QSC : 1.0f;
    const float4* s4 = (const float4*)src + (size_t)r * 64 + c * 2;
    float4 a = s4[0], b = s4[1];
    a.x *= sc; a.y *= sc; a.z *= sc; a.w *= sc;
    b.x *= sc; b.y *= sc; b.z *= sc; b.w *= sc;
    uint32_t h0, l0, h1, l1, h2, l2, h3, l3;
    split_pair(a.x, a.y, h0, l0); split_pair(a.z, a.w, h1, l1);
    split_pair(b.x, b.y, h2, l2); split_pair(b.z, b.w, h3, l3);
    uint4 hi4 = make_uint4(h0, h1, h2, h3);
    uint4 lo4 = make_uint4(l0, l1, l2, l3);
    int off = r * 32 + (c ^ (r & 7));
    if (t == 0) {
        gQ16[off] = hi4;
    } else if (t == 1) {
        gKH[off] = hi4; gKL[off] = lo4;
    } else {
        gVH[off] = hi4; gVL[off] = lo4;
    }
}

// ---------------- main attention kernel ----------------
__global__ __launch_bounds__(NTH, 1)
void attn_mma(const int* __restrict__ pad, float* __restrict__ Og) {
    extern __shared__ char smem[];
    const uint32_t smb = smem_u32(smem);
    const int tid = threadIdx.x, lane = tid & 31, wid = tid >> 5;
    const int wr = wid & 3;         // row-group: rows 16*wr .. 16*wr+15
    const int h  = wid >> 2;        // column half
    const int bx = blockIdx.x;
    const int qt = 31 - (bx >> 4);  // big q-tiles first (LPT)
    const int b  = bx & 15;

    float* pmax = (float*)(smem + SM_PMAX);
    float* psum = (float*)(smem + SM_PSUM);
    int*  padsm = (int*)(smem + SM_PADS);

    // prologue: Q (group) then K(0) (group)
    {
        const uint4* q1 = gQ16 + (size_t)(b * SEQ + qt * 64) * 32;
        for (int g = tid; g < 2048; g += NTH)
            cpa16(smb + SM_Q16 + g * 16, q1 + g);
        CP_COMMIT();
        const uint4* kh = gKH + (size_t)(b * SEQ) * 32;
        const uint4* kl = gKL + (size_t)(b * SEQ) * 32;
        for (int g = tid; g < 2048; g += NTH) {
            cpa16(smb + SM_KH + g * 16, kh + g);
            cpa16(smb + SM_KL + g * 16, kl + g);
        }
        CP_COMMIT();
    }

    float o[16][4];
#pragma unroll
    for (int i = 0; i < 16; i++) { o[i][0] = 0.f; o[i][1] = 0.f; o[i][2] = 0.f; o[i][3] = 0.f; }
    float mA = -INFINITY, mB = -INFINITY, lA = 0.f, lB = 0.f;
    const int rloc = 16 * wr + (lane >> 2);   // local q-row A; row B = +8
    const int grA  = qt * 64 + rloc;

    const int ntiles = qt + 1;
    for (int j0 = 0; j0 < ntiles; ++j0) {
        __syncthreads();  // sync#1: PV(j0-1) done reading V
        {   // issue V(j0)
            const uint4* vh = gVH + (size_t)(b * SEQ + j0 * 64) * 32;
            const uint4* vl = gVL + (size_t)(b * SEQ + j0 * 64) * 32;
            for (int g = tid; g < 2048; g += NTH) {
                cpa16(smb + SM_VH + g * 16, vh + g);
                cpa16(smb + SM_VL + g * 16, vl + g);
            }
            CP_COMMIT();
        }
        if (tid < 64) padsm[tid] = pad[(size_t)b * SEQ + (size_t)j0 * 64 + tid];
        CP_WAIT(1);       // K(j0) (and Q on iter 0) complete; V(j0) in flight
        __syncthreads();  // sync#2

        // ---- S = Q16*Kh + Q16*Kl  (16 rows x 32 cols per warp) ----
        float s[4][4];
#pragma unroll
        for (int j = 0; j < 4; j++) { s[j][0] = 0.f; s[j][1] = 0.f; s[j][2] = 0.f; s[j][3] = 0.f; }
        {
            const int qr = 16 * wr + (lane & 15);
            const int qc = (lane >> 4) & 1;
            const int krow = 32 * h + (lane & 7) + (((lane >> 4) & 1) << 3);
            const int kc = (lane >> 3) & 1;
#pragma unroll
            for (int ks = 0; ks < 16; ks++) {
                uint32_t q[4];
                uint32_t qsw = (uint32_t)(((2 * ks + qc) ^ (qr & 7)) << 4);
                ldsm4(q, smb + SM_Q16 + qr * 512 + qsw);
                uint32_t csw = (uint32_t)(((2 * ks + kc) ^ (lane & 7)) << 4);
                uint32_t kh0[4], kh1[4], kl0[4], kl1[4];
                ldsm4(kh0, smb + SM_KH + krow * 512 + csw);
                ldsm4(kh1, smb + SM_KH + (krow + 16) * 512 + csw);
                ldsm4(kl0, smb + SM_KL + krow * 512 + csw);
                ldsm4(kl1, smb + SM_KL + (krow + 16) * 512 + csw);
                mmah(s[0], q, kh0[0], kh0[1]);
                mmah(s[0], q, kl0[0], kl0[1]);
                mmah(s[1], q, kh0[2], kh0[3]);
                mmah(s[1], q, kl0[2], kl0[3]);
                mmah(s[2], q, kh1[0], kh1[1]);
                mmah(s[2], q, kl1[0], kl1[1]);
                mmah(s[3], q, kh1[2], kh1[3]);
                mmah(s[3], q, kl1[2], kl1[3]);
            }
        }

        // ---- mask + rowmax ----
        uint32_t pm0 = __ballot_sync(0xffffffffu, padsm[lane] != 0);
        uint32_t pm1 = __ballot_sync(0xffffffffu, padsm[lane + 32] != 0);
        const uint32_t pmsel = h ? pm1 : pm0;
        const int limA = grA - j0 * 64 - 32 * h;
        const int limB = limA + 8;
        const int cb = (lane & 3) * 2;
        float rmA = -INFINITY, rmB = -INFINITY;
#pragma unroll
        for (int j = 0; j < 4; j++) {
#pragma unroll
            for (int e = 0; e < 2; e++) {
                const int cl = 8 * j + cb + e;
                const bool okp = (pmsel >> cl) & 1u;
                float v = s[j][e];
                if (cl > limA || !okp) v = -INFINITY;
                s[j][e] = v; rmA = fmaxf(rmA, v);
                float w = s[j][2 + e];
                if (cl > limB || !okp) w = -INFINITY;
                s[j][2 + e] = w; rmB = fmaxf(rmB, w);
            }
        }
        rmA = fmaxf(rmA, __shfl_xor_sync(0xffffffffu, rmA, 1));
        rmA = fmaxf(rmA, __shfl_xor_sync(0xffffffffu, rmA, 2));
        rmB = fmaxf(rmB, __shfl_xor_sync(0xffffffffu, rmB, 1));
        rmB = fmaxf(rmB, __shfl_xor_sync(0xffffffffu, rmB, 2));
        if ((lane & 3) == 0) {
            pmax[h * 64 + rloc] = rmA;
            pmax[h * 64 + rloc + 8] = rmB;
        }
        PAIR_BAR(wr);     // pmax exchange within warp pair

        // ---- softmax + P (fp16) -> smem ----
        const float nmA = fmaxf(mA, fmaxf(pmax[rloc], pmax[64 + rloc]));
        const float nmB = fmaxf(mB, fmaxf(pmax[rloc + 8], pmax[64 + rloc + 8]));
        const float corrA = (nmA == -INFINITY) ? 1.f : ex2(mA - nmA);
        const float corrB = (nmB == -INFINITY) ? 1.f : ex2(mB - nmB);
        const float nmsA = (nmA == -INFINITY) ? 0.f : nmA;
        const float nmsB = (nmB == -INFINITY) ? 0.f : nmB;
        float sumA = 0.f, sumB = 0.f;
#pragma unroll
        for (int j = 0; j < 4; j++) {
            float p0 = ex2(s[j][0] - nmsA);
            float p1 = ex2(s[j][1] - nmsA);
            float p2 = ex2(s[j][2] - nmsB);
            float p3 = ex2(s[j][3] - nmsB);
            sumA += p0 + p1; sumB += p2 + p3;
            uint32_t phA = packh(p0, p1);
            uint32_t phB = packh(p2, p3);
            const int ch = 4 * h + j;
            const uint32_t offA = rloc * 128 + ((ch ^ (rloc & 7)) << 4) + (lane & 3) * 4;
            const uint32_t offB = offA + 8 * 128;
            *(uint32_t*)(smem + SM_PH + offA) = phA;
            *(uint32_t*)(smem + SM_PH + offB) = phB;
        }
        sumA += __shfl_xor_sync(0xffffffffu, sumA, 1);
        sumA += __shfl_xor_sync(0xffffffffu, sumA, 2);
        sumB += __shfl_xor_sync(0xffffffffu, sumB, 1);
        sumB += __shfl_xor_sync(0xffffffffu, sumB, 2);
        if ((lane & 3) == 0) {
            psum[h * 64 + rloc] = sumA;
            psum[h * 64 + rloc + 8] = sumB;
        }
        PAIR_BAR(wr);     // psum + P visible within pair

        lA = lA * corrA + psum[rloc] + psum[64 + rloc];
        lB = lB * corrB + psum[rloc + 8] + psum[64 + rloc + 8];
        mA = nmA; mB = nmB;
#pragma unroll
        for (int nt = 0; nt < 16; nt++) {
            o[nt][0] *= corrA; o[nt][1] *= corrA;
            o[nt][2] *= corrB; o[nt][3] *= corrB;
        }

        CP_WAIT(0);       // V(j0) complete
        __syncthreads();  // sync#3: S done (K free), V + P visible CTA-wide

        if (j0 + 1 < ntiles) {  // issue K(j0+1); latency hides under PV
            const uint4* kh = gKH + (size_t)(b * SEQ + (j0 + 1) * 64) * 32;
            const uint4* kl = gKL + (size_t)(b * SEQ + (j0 + 1) * 64) * 32;
            for (int g = tid; g < 2048; g += NTH) {
                cpa16(smb + SM_KH + g * 16, kh + g);
                cpa16(smb + SM_KL + g * 16, kl + g);
            }
        }
        CP_COMMIT();

        // ---- O += P16*Vh + P16*Vl  (16 rows x 128 cols per warp) ----
        {
            const int pr = 16 * wr + (lane & 15);
            const int pc = (lane >> 4) & 1;
            const int vrow = (lane & 7) + (((lane >> 3) & 1) << 3);
            const int vca = (lane >> 4) & 1;
#pragma unroll
            for (int ks = 0; ks < 4; ks++) {
                uint32_t p[4];
                const uint32_t poff = (uint32_t)(pr * 128 + (((2 * ks + pc) ^ (pr & 7)) << 4));
                ldsm4(p, smb + SM_PH + poff);
                const uint32_t vbase = (uint32_t)((16 * ks + vrow) * 512);
#pragma unroll
                for (int np = 0; np < 8; np++) {
                    const int c0 = 16 * h + 2 * np + vca;
                    const uint32_t voff = vbase + (uint32_t)(((c0 ^ (lane & 7)) << 4));
                    uint32_t vh[4], vl[4];
                    ldsm4t(vh, smb + SM_VH + voff);
                    ldsm4t(vl, smb + SM_VL + voff);
                    mmah(o[2 * np], p, vh[0], vh[1]);
                    mmah(o[2 * np], p, vl[0], vl[1]);
                    mmah(o[2 * np + 1], p, vh[2], vh[3]);
                    mmah(o[2 * np + 1], p, vl[2], vl[3]);
                }
            }
        }
    }

    // ---- epilogue ----
    const float invA = 1.0f / lA;
    const float invB = 1.0f / lB;
    const size_t rowA = (size_t)b * SEQ + (size_t)(qt * 64 + rloc);
    float* oa = Og + rowA * DIM + 128 * h + (lane & 3) * 2;
    float* ob = oa + 8 * DIM;
#pragma unroll
    for (int nt = 0; nt < 16; nt++) {
        float2 va = make_float2(o[nt][0] * invA, o[nt][1] * invA);
        float2 vb = make_float2(o[nt][2] * invB, o[nt][3] * invB);
        *(float2*)(oa + 8 * nt) = va;
        *(float2*)(ob + 8 * nt) = vb;
    }
}

extern "C" void kernel_launch(void* const* d_in, const int* in_sizes, int n_in,
                              void* d_out, int out_size) {
    const float* Q   = (const float*)d_in[0];
    const float* K   = (const float*)d_in[1];
    const float* V   = (const float*)d_in[2];
    const int*   pad = (const int*)d_in[3];
    float*       O   = (float*)d_out;

    prepass<<<12288, 256>>>(Q, K, V);
    cudaFuncSetAttribute(attn_mma, cudaFuncAttributeMaxDynamicSharedMemorySize, SMEM_TOTAL);
    attn_mma<<<512, NTH, SMEM_TOTAL>>>(pad, O);
}